// round 2
// baseline (speedup 1.0000x reference)
#include <cuda_runtime.h>
#include <cuda_fp16.h>
#include <stdint.h>

// ============================================================================
// GRU cell via legacy mma.sync (HMMA) — tcgen05 is NOT available at the
// bench's PTX target (plain sm_103, no 'a' suffix; verified by R1 ptxas log).
//   r = sigmoid(x@wx_r + hid@wh_r + bx_r + bh_r)
//   z = sigmoid(x@wx_z + hid@wh_z + bx_z + bh_z)
//   n = tanh((x@wx_n + bx_n) + r*(hid@wh_n + bh_n))
//   out = (1-z)*n + z*hid
// B=8192, I=H=1024.  fp16 operands, fp32 accum, 4 register accumulators.
// CTA tile 128x64, warp tile 32x32, KC=32, 4-stage cp.async pipeline.
// ============================================================================

#define TM 128
#define TN 64
#define KC 32
#define STAGES 4
#define NCH 64                 // 2048 / 32 (32 x-chunks + 32 hid-chunks)
#define A_BYTES 10240          // 128 rows * 80B (pitch 40 halves)
#define WG_BYTES 5120          // 64 rows * 80B
#define STG (A_BYTES + 3 * WG_BYTES)   // 25600
#define SMEM_DYN (1024 + STAGES * STG) // 103424

// fp16 staging (device globals = allocation-free scratch)
__device__ __half g_xh[8192u * 1024u];
__device__ __half g_hh[8192u * 1024u];
__device__ __half g_wxh[3u * 1024u * 1024u];   // [g][h][i] (transposed: n-major, k contiguous)
__device__ __half g_whh[3u * 1024u * 1024u];

// ---------------------------------------------------------------- helpers ---
__device__ __forceinline__ uint32_t smem_u32(const void* p) {
    uint32_t a;
    asm("{ .reg .u64 t; cvta.to.shared.u64 t, %1; cvt.u32.u64 %0, t; }"
        : "=r"(a) : "l"(p));
    return a;
}

__device__ __forceinline__ void cp16(uint32_t dst, const void* src) {
    asm volatile("cp.async.cg.shared.global [%0], [%1], 16;\n"
                 :: "r"(dst), "l"(src));
}

__device__ __forceinline__ void ldsm4(uint32_t* r, uint32_t addr) {
    asm volatile("ldmatrix.sync.aligned.m8n8.x4.shared.b16 {%0,%1,%2,%3}, [%4];"
                 : "=r"(r[0]), "=r"(r[1]), "=r"(r[2]), "=r"(r[3]) : "r"(addr));
}

__device__ __forceinline__ void mma16816(float* c, const uint32_t* a, const uint32_t* b) {
    asm volatile(
        "mma.sync.aligned.m16n8k16.row.col.f32.f16.f16.f32 "
        "{%0,%1,%2,%3}, {%4,%5,%6,%7}, {%8,%9}, {%0,%1,%2,%3};"
        : "+f"(c[0]), "+f"(c[1]), "+f"(c[2]), "+f"(c[3])
        : "r"(a[0]), "r"(a[1]), "r"(a[2]), "r"(a[3]), "r"(b[0]), "r"(b[1]));
}

// --------------------------------------------------------- convert kernels ---
__global__ void k_convert(const float* __restrict__ x, const float* __restrict__ hid) {
    const float* src = blockIdx.y ? hid : x;
    __half* dst = blockIdx.y ? g_hh : g_xh;
    size_t i = ((size_t)blockIdx.x * blockDim.x + threadIdx.x) * 4;
    float4 v = *reinterpret_cast<const float4*>(src + i);
    *reinterpret_cast<__half2*>(dst + i)     = __floats2half2_rn(v.x, v.y);
    *reinterpret_cast<__half2*>(dst + i + 2) = __floats2half2_rn(v.z, v.w);
}

__global__ void k_wtrans(const float* __restrict__ wx, const float* __restrict__ wh) {
    __shared__ float tile[32][33];
    int m = blockIdx.z;
    const float* src = (m < 3) ? (wx + (size_t)m * 1048576)
                               : (wh + (size_t)(m - 3) * 1048576);
    __half* dst = ((m < 3) ? g_wxh : g_whh) + (size_t)(m % 3) * 1048576;
    int h0 = blockIdx.x * 32, i0 = blockIdx.y * 32;
    int tx = threadIdx.x, ty = threadIdx.y;
#pragma unroll
    for (int j = 0; j < 32; j += 8)
        tile[ty + j][tx] = src[(size_t)(i0 + ty + j) * 1024 + h0 + tx];
    __syncthreads();
#pragma unroll
    for (int j = 0; j < 32; j += 8)
        dst[(size_t)(h0 + ty + j) * 1024 + i0 + tx] = __float2half_rn(tile[tx][ty + j]);
}

// ------------------------------------------------------------- GEMM kernel ---
// SMEM: [0,1024) bias arrays sb[4][64] fp32; stages at +1024, each STG bytes:
//   A tile [128][40 halves] (pitch 80B), then 3 W tiles [64][40 halves].
// accum acc[slot][mt][nt][4]: slot 0=r, 1=z, 2=gx_n, 3=gh_n.

template<int NS>
__device__ __forceinline__ void compute_chunk(float (&acc)[4][2][4][4],
                                              uint32_t st, int lid, int wm, int wn) {
#pragma unroll
    for (int ks = 0; ks < 2; ks++) {
        uint32_t af[2][4];
#pragma unroll
        for (int mt = 0; mt < 2; mt++) {
            uint32_t arow = wm * 32 + mt * 16 + (lid & 15);
            ldsm4(af[mt], st + arow * 80 + ks * 32 + (lid >> 4) * 16);
        }
#pragma unroll
        for (int g = 0; g < 3; g++) {
            const int slot = (g == 0) ? 0 : (g == 1) ? 1 : NS;
            uint32_t wg = st + A_BYTES + g * WG_BYTES;
            uint32_t bf[2][4];
#pragma unroll
            for (int p = 0; p < 2; p++) {
                uint32_t wrow = wn * 32 + p * 16 + (lid & 7) + ((lid & 16) >> 1);
                ldsm4(bf[p], wg + wrow * 80 + ((lid >> 3) & 1) * 16 + ks * 32);
            }
#pragma unroll
            for (int mt = 0; mt < 2; mt++)
#pragma unroll
                for (int nt = 0; nt < 4; nt++)
                    mma16816(acc[slot][mt][nt], af[mt], &bf[nt >> 1][(nt & 1) * 2]);
        }
    }
}

__device__ __forceinline__ void load_stage(int ch, int tid, int m0, int n0, uint32_t stg0) {
    const __half* asrc = (ch < 32) ? g_xh : g_hh;
    const __half* wsrc = (ch < 32) ? g_wxh : g_whh;
    int k0 = (ch & 31) * KC;
    uint32_t st = stg0 + (uint32_t)(ch & (STAGES - 1)) * STG;
#pragma unroll
    for (int q = 0; q < 2; q++) {
        int op = tid + q * 256, row = op >> 2, cg = op & 3;
        cp16(st + row * 80 + cg * 16,
             asrc + (size_t)(m0 + row) * 1024 + k0 + cg * 8);
    }
#pragma unroll
    for (int q = 0; q < 3; q++) {
        int op = tid + q * 256, g = op >> 8, r = (op >> 2) & 63, cg = op & 3;
        cp16(st + A_BYTES + g * WG_BYTES + r * 80 + cg * 16,
             wsrc + (size_t)g * 1048576 + (size_t)(n0 + r) * 1024 + k0 + cg * 8);
    }
    asm volatile("cp.async.commit_group;" ::: "memory");
}

__global__ void __launch_bounds__(256, 1)
k_gru(const float* __restrict__ hid,
      const float* __restrict__ bx, const float* __restrict__ bh,
      float* __restrict__ out) {
    extern __shared__ char smem[];
    const uint32_t sbase = smem_u32(smem);
    const uint32_t stg0 = sbase + 1024;

    const int tid = threadIdx.x;
    const int lid = tid & 31;
    const int wid = tid >> 5;
    const int wm = wid & 3;          // warp m index (4)
    const int wn = wid >> 2;         // warp n index (2)
    const int m0 = blockIdx.y * TM;
    const int n0 = blockIdx.x * TN;

    // bias staging: r-sum, z-sum, gx_n bias, gh_n bias (cols n0..n0+63)
    float* sb = reinterpret_cast<float*>(smem);
    if (tid < 64) {
        int h = n0 + tid;
        sb[tid]       = bx[h]        + bh[h];
        sb[64 + tid]  = bx[1024 + h] + bh[1024 + h];
        sb[128 + tid] = bx[2048 + h];
        sb[192 + tid] = bh[2048 + h];
    }

    float acc[4][2][4][4];
#pragma unroll
    for (int s = 0; s < 4; s++)
#pragma unroll
        for (int mt = 0; mt < 2; mt++)
#pragma unroll
            for (int nt = 0; nt < 4; nt++)
#pragma unroll
                for (int r = 0; r < 4; r++) acc[s][mt][nt][r] = 0.f;

    load_stage(0, tid, m0, n0, stg0);
    load_stage(1, tid, m0, n0, stg0);
    load_stage(2, tid, m0, n0, stg0);

    for (int ch = 0; ch < NCH; ++ch) {
        if (ch <= NCH - 3)      asm volatile("cp.async.wait_group 2;" ::: "memory");
        else if (ch == NCH - 2) asm volatile("cp.async.wait_group 1;" ::: "memory");
        else                    asm volatile("cp.async.wait_group 0;" ::: "memory");
        __syncthreads();
        if (ch + 3 < NCH) load_stage(ch + 3, tid, m0, n0, stg0);
        uint32_t st = stg0 + (uint32_t)(ch & (STAGES - 1)) * STG;
        if (ch < 32) compute_chunk<2>(acc, st, lid, wm, wn);
        else         compute_chunk<3>(acc, st, lid, wm, wn);
    }

    // ---- fused GRU epilogue ----
    const int g4 = lid >> 2, t4 = lid & 3;
#pragma unroll
    for (int mt = 0; mt < 2; mt++)
#pragma unroll
        for (int nt = 0; nt < 4; nt++)
#pragma unroll
            for (int hf = 0; hf < 2; hf++) {
                int row = m0 + wm * 32 + mt * 16 + g4 + hf * 8;
                int coll = wn * 32 + nt * 8 + t4 * 2;
                size_t base = (size_t)row * 1024 + n0 + coll;
                float2 h2 = *reinterpret_cast<const float2*>(hid + base);
                float o[2];
#pragma unroll
                for (int j = 0; j < 2; j++) {
                    int ri = hf * 2 + j;
                    float pr = acc[0][mt][nt][ri] + sb[coll + j];
                    float pz = acc[1][mt][nt][ri] + sb[64 + coll + j];
                    float rr = __fdividef(1.f, 1.f + __expf(-pr));
                    float zz = __fdividef(1.f, 1.f + __expf(-pz));
                    float pn = (acc[2][mt][nt][ri] + sb[128 + coll + j])
                             + rr * (acc[3][mt][nt][ri] + sb[192 + coll + j]);
                    float t  = __expf(-2.f * fabsf(pn));
                    float nn = copysignf(__fdividef(1.f - t, 1.f + t), pn);
                    float hv = j ? h2.y : h2.x;
                    o[j] = nn + zz * (hv - nn);
                }
                float2 o2 = make_float2(o[0], o[1]);
                *reinterpret_cast<float2*>(out + base) = o2;
            }
}

// --------------------------------------------------------------- launcher ---
extern "C" void kernel_launch(void* const* d_in, const int* in_sizes, int n_in,
                              void* d_out, int out_size) {
    const float* x   = (const float*)d_in[0];
    const float* hid = (const float*)d_in[1];
    const float* wx  = (const float*)d_in[2];
    const float* wh  = (const float*)d_in[3];
    const float* bx  = (const float*)d_in[4];
    const float* bh  = (const float*)d_in[5];
    float* out = (float*)d_out;

    cudaFuncSetAttribute(k_gru, cudaFuncAttributeMaxDynamicSharedMemorySize, SMEM_DYN);

    // fp16 conversion: activations (8192x1024 each), 4 elems/thread
    k_convert<<<dim3(8192, 2), 256>>>(x, hid);
    // weight transpose+convert: 6 matrices 1024x1024 -> [g][h][i] fp16
    k_wtrans<<<dim3(32, 32, 6), dim3(32, 8)>>>(wx, wh);
    // fused GEMM + GRU epilogue: 16 n-tiles x 64 m-tiles
    k_gru<<<dim3(16, 64), 256, SMEM_DYN>>>(hid, bx, bh, out);
}

// round 4
// speedup vs baseline: 1.4712x; 1.4712x over previous
#include <cuda_runtime.h>
#include <cuda_fp16.h>
#include <stdint.h>

// ============================================================================
// GRU cell via legacy mma.sync (tcgen05 unavailable at plain-sm_103 PTX target,
// verified R1). Round 4: warp-specialized pipeline, FIXED mbarrier arming —
// cp.async.mbarrier.arrive must be the .noinc form to consume an expected
// arrival (default form is net-zero on pending count -> R3 deadlock).
//   r = sigmoid(x@wx_r + hid@wh_r + b...)
//   z = sigmoid(x@wx_z + hid@wh_z + b...)
//   n = tanh((x@wx_n + bx_n) + r*(hid@wh_n + bh_n))
//   out = (1-z)*n + z*hid
// B=8192, I=H=1024. fp16 operands, fp32 accum, 4 register accumulator slots.
// CTA tile 128x64: 8 consumer warps (32x32 each) + 2 producer warps.
// KC=32, 4-stage cp.async pipeline gated by mbarrier full/empty pairs.
// ============================================================================

#define TM 128
#define TN 64
#define KC 32
#define STAGES 4
#define NCH 64                 // 2048/32: chunks 0..31 = x-phase, 32..63 = hid
#define A_BYTES 10240          // 128 rows * 80B (pitch 40 halves)
#define WG_BYTES 5120          // 64 rows * 80B
#define STG (A_BYTES + 3 * WG_BYTES)       // 25600
#define SMEM_DYN (2048 + STAGES * STG)     // 104448

#define NTHREADS 320           // 8 consumer warps + 2 producer warps

// fp16 staging (device globals = allocation-free scratch)
__device__ __half g_xh[8192u * 1024u];
__device__ __half g_hh[8192u * 1024u];
__device__ __half g_wxh[3u * 1024u * 1024u];   // [g][h][i] (k contiguous)
__device__ __half g_whh[3u * 1024u * 1024u];

// ---------------------------------------------------------------- helpers ---
__device__ __forceinline__ uint32_t smem_u32(const void* p) {
    uint32_t a;
    asm("{ .reg .u64 t; cvta.to.shared.u64 t, %1; cvt.u32.u64 %0, t; }"
        : "=r"(a) : "l"(p));
    return a;
}

__device__ __forceinline__ void cp16(uint32_t dst, const void* src) {
    asm volatile("cp.async.cg.shared.global [%0], [%1], 16;\n"
                 :: "r"(dst), "l"(src));
}

__device__ __forceinline__ void ldsm4(uint32_t* r, uint32_t addr) {
    asm volatile("ldmatrix.sync.aligned.m8n8.x4.shared.b16 {%0,%1,%2,%3}, [%4];"
                 : "=r"(r[0]), "=r"(r[1]), "=r"(r[2]), "=r"(r[3]) : "r"(addr));
}

__device__ __forceinline__ void mma16816(float* c, const uint32_t* a, const uint32_t* b) {
    asm volatile(
        "mma.sync.aligned.m16n8k16.row.col.f32.f16.f16.f32 "
        "{%0,%1,%2,%3}, {%4,%5,%6,%7}, {%8,%9}, {%0,%1,%2,%3};"
        : "+f"(c[0]), "+f"(c[1]), "+f"(c[2]), "+f"(c[3])
        : "r"(a[0]), "r"(a[1]), "r"(a[2]), "r"(a[3]), "r"(b[0]), "r"(b[1]));
}

__device__ __forceinline__ void mbar_wait(uint32_t mbar, uint32_t parity) {
    asm volatile(
        "{\n\t.reg .pred P1;\n\t"
        "WL_%=:\n\t"
        "mbarrier.try_wait.parity.acquire.cta.shared::cta.b64 P1, [%0], %1, 0x989680;\n\t"
        "@P1 bra.uni WD_%=;\n\t"
        "bra.uni WL_%=;\n\t"
        "WD_%=:\n\t}"
        :: "r"(mbar), "r"(parity) : "memory");
}

__device__ __forceinline__ void mbar_arrive(uint32_t mbar) {
    asm volatile("mbarrier.arrive.shared.b64 _, [%0];" :: "r"(mbar) : "memory");
}

// --------------------------------------------------------- convert kernels ---
__global__ void k_convert(const float* __restrict__ x, const float* __restrict__ hid) {
    const float* src = blockIdx.y ? hid : x;
    __half* dst = blockIdx.y ? g_hh : g_xh;
    size_t i = ((size_t)blockIdx.x * blockDim.x + threadIdx.x) * 4;
    float4 v = *reinterpret_cast<const float4*>(src + i);
    *reinterpret_cast<__half2*>(dst + i)     = __floats2half2_rn(v.x, v.y);
    *reinterpret_cast<__half2*>(dst + i + 2) = __floats2half2_rn(v.z, v.w);
}

__global__ void k_wtrans(const float* __restrict__ wx, const float* __restrict__ wh) {
    __shared__ float tile[32][33];
    int m = blockIdx.z;
    const float* src = (m < 3) ? (wx + (size_t)m * 1048576)
                               : (wh + (size_t)(m - 3) * 1048576);
    __half* dst = ((m < 3) ? g_wxh : g_whh) + (size_t)(m % 3) * 1048576;
    int h0 = blockIdx.x * 32, i0 = blockIdx.y * 32;
    int tx = threadIdx.x, ty = threadIdx.y;
#pragma unroll
    for (int j = 0; j < 32; j += 8)
        tile[ty + j][tx] = src[(size_t)(i0 + ty + j) * 1024 + h0 + tx];
    __syncthreads();
#pragma unroll
    for (int j = 0; j < 32; j += 8)
        dst[(size_t)(h0 + ty + j) * 1024 + i0 + tx] = __float2half_rn(tile[tx][ty + j]);
}

// ------------------------------------------------------------- GEMM kernel ---
// SMEM: [0,1024)    bias sb[4][64] fp32
//       [1024,1088) mbarriers: full[s]=1024+16s, empty[s]=1032+16s
//       [2048, ...) stages, each STG bytes: A[128][40h] pitch 80B, then 3 W[64][40h]
// acc slots: 0=r, 1=z, 2=gx_n, 3=gh_n.

template<int NS>
__device__ __forceinline__ void compute_chunk(float (&acc)[4][2][4][4],
                                              uint32_t st, int lid, int wm, int wn) {
#pragma unroll
    for (int ks = 0; ks < 2; ks++) {
        uint32_t af[2][4];
#pragma unroll
        for (int mt = 0; mt < 2; mt++) {
            uint32_t arow = wm * 32 + mt * 16 + (lid & 15);
            ldsm4(af[mt], st + arow * 80 + ks * 32 + (lid >> 4) * 16);
        }
#pragma unroll
        for (int g = 0; g < 3; g++) {
            const int slot = (g == 0) ? 0 : (g == 1) ? 1 : NS;
            uint32_t wg = st + A_BYTES + g * WG_BYTES;
            uint32_t bf[2][4];
#pragma unroll
            for (int p = 0; p < 2; p++) {
                uint32_t wrow = wn * 32 + p * 16 + (lid & 7) + ((lid & 16) >> 1);
                ldsm4(bf[p], wg + wrow * 80 + ((lid >> 3) & 1) * 16 + ks * 32);
            }
#pragma unroll
            for (int mt = 0; mt < 2; mt++)
#pragma unroll
                for (int nt = 0; nt < 4; nt++)
                    mma16816(acc[slot][mt][nt], af[mt], &bf[nt >> 1][(nt & 1) * 2]);
        }
    }
}

__global__ void __launch_bounds__(NTHREADS, 1)
k_gru(const float* __restrict__ hid,
      const float* __restrict__ bx, const float* __restrict__ bh,
      float* __restrict__ out) {
    extern __shared__ char smem[];
    const uint32_t sbase = smem_u32(smem);
    const uint32_t mb0 = sbase + 1024;          // full[s]=mb0+16s, empty[s]=mb0+16s+8
    const uint32_t stg0 = sbase + 2048;

    const int tid = threadIdx.x;
    const int lid = tid & 31;
    const int wid = tid >> 5;
    const int m0 = blockIdx.y * TM;
    const int n0 = blockIdx.x * TN;

    float* sb = reinterpret_cast<float*>(smem);
    if (tid < 64) {
        int h = n0 + tid;
        sb[tid]       = bx[h]        + bh[h];
        sb[64 + tid]  = bx[1024 + h] + bh[1024 + h];
        sb[128 + tid] = bx[2048 + h];
        sb[192 + tid] = bh[2048 + h];
    }
    if (tid < STAGES) {
        asm volatile("mbarrier.init.shared.b64 [%0], 64;" :: "r"(mb0 + tid * 16)     : "memory");
        asm volatile("mbarrier.init.shared.b64 [%0], 8;"  :: "r"(mb0 + tid * 16 + 8) : "memory");
    }
    __syncthreads();

    if (wid >= 8) {
        // ---------------- producer warps (2 warps, 64 threads) ----------------
        const int ptid = tid - 256;               // 0..63
        for (int it = 0; it < NCH; ++it) {
            const int s = it & (STAGES - 1);
            const int w = it >> 2;                 // wrap count of stage s
            if (w > 0) mbar_wait(mb0 + s * 16 + 8, (w - 1) & 1);  // empty[s]
            uint32_t st = stg0 + (uint32_t)s * STG;
            const __half* asrc = (it < 32) ? g_xh  : g_hh;
            const __half* wsrc = (it < 32) ? g_wxh : g_whh;
            const int k0 = (it & 31) * KC;
#pragma unroll
            for (int q = 0; q < 8; q++) {          // A: 512 cp16
                int op = ptid + q * 64, row = op >> 2, cg = op & 3;
                cp16(st + row * 80 + cg * 16,
                     asrc + (size_t)(m0 + row) * 1024 + k0 + cg * 8);
            }
#pragma unroll
            for (int q = 0; q < 12; q++) {         // W: 768 cp16
                int op = ptid + q * 64, g = op >> 8, r = (op >> 2) & 63, cg = op & 3;
                cp16(st + A_BYTES + g * WG_BYTES + r * 80 + cg * 16,
                     wsrc + (size_t)g * 1048576 + (size_t)(n0 + r) * 1024 + k0 + cg * 8);
            }
            // .noinc: the async arrive CONSUMES one of the 64 expected arrivals.
            // (Default form is net-zero on the pending count -> R3 deadlock.)
            asm volatile("cp.async.mbarrier.arrive.noinc.shared::cta.b64 [%0];"
                         :: "r"(mb0 + s * 16) : "memory");
        }
        return;
    }

    // ------------------- consumer warps (8 warps, 256 threads) ----------------
    const int wm = wid & 3;
    const int wn = wid >> 2;

    float acc[4][2][4][4];
#pragma unroll
    for (int s = 0; s < 4; s++)
#pragma unroll
        for (int mt = 0; mt < 2; mt++)
#pragma unroll
            for (int nt = 0; nt < 4; nt++)
#pragma unroll
                for (int r = 0; r < 4; r++) acc[s][mt][nt][r] = 0.f;

#pragma unroll 1
    for (int it = 0; it < 32; ++it) {              // x-phase: n-gate -> slot 2
        const int s = it & (STAGES - 1);
        mbar_wait(mb0 + s * 16, (it >> 2) & 1);    // full[s]
        compute_chunk<2>(acc, stg0 + (uint32_t)s * STG, lid, wm, wn);
        if (lid == 0) mbar_arrive(mb0 + s * 16 + 8);
    }
#pragma unroll 1
    for (int it = 32; it < NCH; ++it) {            // hid-phase: n-gate -> slot 3
        const int s = it & (STAGES - 1);
        mbar_wait(mb0 + s * 16, (it >> 2) & 1);
        compute_chunk<3>(acc, stg0 + (uint32_t)s * STG, lid, wm, wn);
        if (lid == 0) mbar_arrive(mb0 + s * 16 + 8);
    }

    // ---- fused GRU epilogue ----
    const int g4 = lid >> 2, t4 = lid & 3;
#pragma unroll
    for (int mt = 0; mt < 2; mt++)
#pragma unroll
        for (int nt = 0; nt < 4; nt++)
#pragma unroll
            for (int hf = 0; hf < 2; hf++) {
                int row = m0 + wm * 32 + mt * 16 + g4 + hf * 8;
                int coll = wn * 32 + nt * 8 + t4 * 2;
                size_t base = (size_t)row * 1024 + n0 + coll;
                float2 h2 = *reinterpret_cast<const float2*>(hid + base);
                float o[2];
#pragma unroll
                for (int j = 0; j < 2; j++) {
                    int ri = hf * 2 + j;
                    float pr = acc[0][mt][nt][ri] + sb[coll + j];
                    float pz = acc[1][mt][nt][ri] + sb[64 + coll + j];
                    float rr = __fdividef(1.f, 1.f + __expf(-pr));
                    float zz = __fdividef(1.f, 1.f + __expf(-pz));
                    float pn = (acc[2][mt][nt][ri] + sb[128 + coll + j])
                             + rr * (acc[3][mt][nt][ri] + sb[192 + coll + j]);
                    float t  = __expf(-2.f * fabsf(pn));
                    float nn = copysignf(__fdividef(1.f - t, 1.f + t), pn);
                    float hv = j ? h2.y : h2.x;
                    o[j] = nn + zz * (hv - nn);
                }
                *reinterpret_cast<float2*>(out + base) = make_float2(o[0], o[1]);
            }
}

// --------------------------------------------------------------- launcher ---
extern "C" void kernel_launch(void* const* d_in, const int* in_sizes, int n_in,
                              void* d_out, int out_size) {
    const float* x   = (const float*)d_in[0];
    const float* hid = (const float*)d_in[1];
    const float* wx  = (const float*)d_in[2];
    const float* wh  = (const float*)d_in[3];
    const float* bx  = (const float*)d_in[4];
    const float* bh  = (const float*)d_in[5];
    float* out = (float*)d_out;

    cudaFuncSetAttribute(k_gru, cudaFuncAttributeMaxDynamicSharedMemorySize, SMEM_DYN);

    k_convert<<<dim3(8192, 2), 256>>>(x, hid);
    k_wtrans<<<dim3(32, 32, 6), dim3(32, 8)>>>(wx, wh);
    k_gru<<<dim3(16, 64), NTHREADS, SMEM_DYN>>>(hid, bx, bh, out);
}

// round 5
// speedup vs baseline: 1.5709x; 1.0678x over previous
#include <cuda_runtime.h>
#include <cuda_fp16.h>
#include <stdint.h>

// ============================================================================
// GRU cell via legacy mma.sync (tcgen05 unavailable at plain-sm_103 PTX target).
// R5: merged pre-pass, KC=64 chunks, 3-stage pipeline (fewer syncs, deeper
// unroll, contiguous cp.async writes).
//   r = sigmoid(x@wx_r + hid@wh_r + b...), z = sigmoid(...),
//   n = tanh((x@wx_n + bx_n) + r*(hid@wh_n + bh_n)), out = (1-z)n + z*hid
// B=8192, I=H=1024. fp16 operands, fp32 accum, 4 register accumulator slots.
// CTA tile 128x64: 8 consumer warps (32x32) + 2 producer warps.
// ============================================================================

#define TM 128
#define TN 64
#define KC 64
#define STAGES 3
#define NCH 32                 // 2048/64: chunks 0..15 = x-phase, 16..31 = hid
#define PITCH 144              // 128B row + 16B pad (conflict-free ldsm)
#define A_BYTES (128 * PITCH)              // 18432
#define WG_BYTES (64 * PITCH)              // 9216
#define STG (A_BYTES + 3 * WG_BYTES)       // 46080
#define SMEM_DYN (2048 + STAGES * STG)     // 140288

#define NTHREADS 320           // 8 consumer warps + 2 producer warps

// fp16 staging (device globals = allocation-free scratch)
__device__ __half g_xh[8192u * 1024u];
__device__ __half g_hh[8192u * 1024u];
__device__ __half g_wxh[3u * 1024u * 1024u];   // [g][h][i] (k contiguous)
__device__ __half g_whh[3u * 1024u * 1024u];

// ---------------------------------------------------------------- helpers ---
__device__ __forceinline__ uint32_t smem_u32(const void* p) {
    uint32_t a;
    asm("{ .reg .u64 t; cvta.to.shared.u64 t, %1; cvt.u32.u64 %0, t; }"
        : "=r"(a) : "l"(p));
    return a;
}

__device__ __forceinline__ void cp16(uint32_t dst, const void* src) {
    asm volatile("cp.async.cg.shared.global [%0], [%1], 16;\n"
                 :: "r"(dst), "l"(src));
}

__device__ __forceinline__ void ldsm4(uint32_t* r, uint32_t addr) {
    asm volatile("ldmatrix.sync.aligned.m8n8.x4.shared.b16 {%0,%1,%2,%3}, [%4];"
                 : "=r"(r[0]), "=r"(r[1]), "=r"(r[2]), "=r"(r[3]) : "r"(addr));
}

__device__ __forceinline__ void mma16816(float* c, const uint32_t* a, const uint32_t* b) {
    asm volatile(
        "mma.sync.aligned.m16n8k16.row.col.f32.f16.f16.f32 "
        "{%0,%1,%2,%3}, {%4,%5,%6,%7}, {%8,%9}, {%0,%1,%2,%3};"
        : "+f"(c[0]), "+f"(c[1]), "+f"(c[2]), "+f"(c[3])
        : "r"(a[0]), "r"(a[1]), "r"(a[2]), "r"(a[3]), "r"(b[0]), "r"(b[1]));
}

__device__ __forceinline__ void mbar_wait(uint32_t mbar, uint32_t parity) {
    asm volatile(
        "{\n\t.reg .pred P1;\n\t"
        "WL_%=:\n\t"
        "mbarrier.try_wait.parity.acquire.cta.shared::cta.b64 P1, [%0], %1, 0x989680;\n\t"
        "@P1 bra.uni WD_%=;\n\t"
        "bra.uni WL_%=;\n\t"
        "WD_%=:\n\t}"
        :: "r"(mbar), "r"(parity) : "memory");
}

__device__ __forceinline__ void mbar_arrive(uint32_t mbar) {
    asm volatile("mbarrier.arrive.shared.b64 _, [%0];" :: "r"(mbar) : "memory");
}

// ----------------------------------------------------- merged pre-pass ------
// blocks [0, 16384): fp32 -> fp16 convert of x (first 8192) and hid.
// blocks [16384, 22528): 6 x 1024-block weight transpose+convert (32x32 tiles).
__global__ void k_prep(const float* __restrict__ x, const float* __restrict__ hid,
                       const float* __restrict__ wx, const float* __restrict__ wh) {
    const int b = blockIdx.x;
    if (b < 16384) {
        const float* src = (b < 8192) ? x : hid;
        __half* dst = (b < 8192) ? g_xh : g_hh;
        size_t i = ((size_t)(b & 8191) * 256 + threadIdx.x) * 4;
        float4 v = *reinterpret_cast<const float4*>(src + i);
        *reinterpret_cast<__half2*>(dst + i)     = __floats2half2_rn(v.x, v.y);
        *reinterpret_cast<__half2*>(dst + i + 2) = __floats2half2_rn(v.z, v.w);
        return;
    }
    __shared__ float tile[32][33];
    const int bb = b - 16384;
    const int m = bb >> 10;                 // 0..5
    const int rem = bb & 1023;
    const int h0 = (rem & 31) * 32;
    const int i0 = (rem >> 5) * 32;
    const float* src = (m < 3) ? (wx + (size_t)m * 1048576)
                               : (wh + (size_t)(m - 3) * 1048576);
    __half* dst = ((m < 3) ? g_wxh : g_whh) + (size_t)(m % 3) * 1048576;
    const int tx = threadIdx.x & 31, ty = threadIdx.x >> 5;   // 32 x 8
#pragma unroll
    for (int j = 0; j < 32; j += 8)
        tile[ty + j][tx] = src[(size_t)(i0 + ty + j) * 1024 + h0 + tx];
    __syncthreads();
#pragma unroll
    for (int j = 0; j < 32; j += 8)
        dst[(size_t)(h0 + ty + j) * 1024 + i0 + tx] = __float2half_rn(tile[tx][ty + j]);
}

// ------------------------------------------------------------- GEMM kernel ---
// SMEM: [0,1024)    bias sb[4][64] fp32
//       [1024,1072) mbarriers: full[s]=1024+16s, empty[s]=1032+16s  (s=0..2)
//       [2048, ...) stages, each STG bytes: A[128][PITCH], then 3 W[64][PITCH]
// acc slots: 0=r, 1=z, 2=gx_n, 3=gh_n.

template<int NS>
__device__ __forceinline__ void compute_chunk(float (&acc)[4][2][4][4],
                                              uint32_t st, int lid, int wm, int wn) {
#pragma unroll
    for (int ks = 0; ks < 4; ks++) {
        uint32_t af[2][4];
#pragma unroll
        for (int mt = 0; mt < 2; mt++) {
            uint32_t arow = wm * 32 + mt * 16 + (lid & 15);
            ldsm4(af[mt], st + arow * PITCH + ks * 32 + (lid >> 4) * 16);
        }
#pragma unroll
        for (int g = 0; g < 3; g++) {
            const int slot = (g == 0) ? 0 : (g == 1) ? 1 : NS;
            uint32_t wg = st + A_BYTES + g * WG_BYTES;
            uint32_t bf[2][4];
#pragma unroll
            for (int p = 0; p < 2; p++) {
                uint32_t wrow = wn * 32 + p * 16 + (lid & 7) + ((lid & 16) >> 1);
                ldsm4(bf[p], wg + wrow * PITCH + ((lid >> 3) & 1) * 16 + ks * 32);
            }
#pragma unroll
            for (int mt = 0; mt < 2; mt++)
#pragma unroll
                for (int nt = 0; nt < 4; nt++)
                    mma16816(acc[slot][mt][nt], af[mt], &bf[nt >> 1][(nt & 1) * 2]);
        }
    }
}

__global__ void __launch_bounds__(NTHREADS, 1)
k_gru(const float* __restrict__ hid,
      const float* __restrict__ bx, const float* __restrict__ bh,
      float* __restrict__ out) {
    extern __shared__ char smem[];
    const uint32_t sbase = smem_u32(smem);
    const uint32_t mb0 = sbase + 1024;          // full[s]=mb0+16s, empty[s]=mb0+16s+8
    const uint32_t stg0 = sbase + 2048;

    const int tid = threadIdx.x;
    const int lid = tid & 31;
    const int wid = tid >> 5;
    const int m0 = blockIdx.y * TM;
    const int n0 = blockIdx.x * TN;

    float* sb = reinterpret_cast<float*>(smem);
    if (tid < 64) {
        int h = n0 + tid;
        sb[tid]       = bx[h]        + bh[h];
        sb[64 + tid]  = bx[1024 + h] + bh[1024 + h];
        sb[128 + tid] = bx[2048 + h];
        sb[192 + tid] = bh[2048 + h];
    }
    if (tid < STAGES) {
        asm volatile("mbarrier.init.shared.b64 [%0], 64;" :: "r"(mb0 + tid * 16)     : "memory");
        asm volatile("mbarrier.init.shared.b64 [%0], 8;"  :: "r"(mb0 + tid * 16 + 8) : "memory");
    }
    __syncthreads();

    if (wid >= 8) {
        // ---------------- producer warps (2 warps, 64 threads) ----------------
        const int ptid = tid - 256;               // 0..63
        for (int it = 0; it < NCH; ++it) {
            const int s = it % STAGES;
            const int rnd = it / STAGES;           // reuse round of stage s
            if (rnd > 0) mbar_wait(mb0 + s * 16 + 8, (rnd - 1) & 1);  // empty[s]
            uint32_t st = stg0 + (uint32_t)s * STG;
            const __half* asrc = (it < 16) ? g_xh  : g_hh;
            const __half* wsrc = (it < 16) ? g_wxh : g_whh;
            const int k0 = (it & 15) * KC;
#pragma unroll
            for (int q = 0; q < 16; q++) {         // A: 1024 cp16 (128 rows x 8)
                int op = ptid + q * 64, row = op >> 3, cg = op & 7;
                cp16(st + row * PITCH + cg * 16,
                     asrc + (size_t)(m0 + row) * 1024 + k0 + cg * 8);
            }
#pragma unroll
            for (int q = 0; q < 24; q++) {         // W: 1536 cp16 (3 x 64 x 8)
                int op = ptid + q * 64, g = op >> 9, r = (op >> 3) & 63, cg = op & 7;
                cp16(st + A_BYTES + g * WG_BYTES + r * PITCH + cg * 16,
                     wsrc + (size_t)g * 1048576 + (size_t)(n0 + r) * 1024 + k0 + cg * 8);
            }
            // .noinc consumes one of the 64 expected arrivals on full[s]
            asm volatile("cp.async.mbarrier.arrive.noinc.shared::cta.b64 [%0];"
                         :: "r"(mb0 + s * 16) : "memory");
        }
        return;
    }

    // ------------------- consumer warps (8 warps, 256 threads) ----------------
    const int wm = wid & 3;
    const int wn = wid >> 2;

    float acc[4][2][4][4];
#pragma unroll
    for (int s = 0; s < 4; s++)
#pragma unroll
        for (int mt = 0; mt < 2; mt++)
#pragma unroll
            for (int nt = 0; nt < 4; nt++)
#pragma unroll
                for (int r = 0; r < 4; r++) acc[s][mt][nt][r] = 0.f;

#pragma unroll 1
    for (int it = 0; it < 16; ++it) {              // x-phase: n-gate -> slot 2
        const int s = it % STAGES;
        mbar_wait(mb0 + s * 16, (it / STAGES) & 1);    // full[s]
        compute_chunk<2>(acc, stg0 + (uint32_t)s * STG, lid, wm, wn);
        if (lid == 0) mbar_arrive(mb0 + s * 16 + 8);
    }
#pragma unroll 1
    for (int it = 16; it < NCH; ++it) {            // hid-phase: n-gate -> slot 3
        const int s = it % STAGES;
        mbar_wait(mb0 + s * 16, (it / STAGES) & 1);
        compute_chunk<3>(acc, stg0 + (uint32_t)s * STG, lid, wm, wn);
        if (lid == 0) mbar_arrive(mb0 + s * 16 + 8);
    }

    // ---- fused GRU epilogue ----
    const int g4 = lid >> 2, t4 = lid & 3;
#pragma unroll
    for (int mt = 0; mt < 2; mt++)
#pragma unroll
        for (int nt = 0; nt < 4; nt++)
#pragma unroll
            for (int hf = 0; hf < 2; hf++) {
                int row = m0 + wm * 32 + mt * 16 + g4 + hf * 8;
                int coll = wn * 32 + nt * 8 + t4 * 2;
                size_t base = (size_t)row * 1024 + n0 + coll;
                float2 h2 = *reinterpret_cast<const float2*>(hid + base);
                float o[2];
#pragma unroll
                for (int j = 0; j < 2; j++) {
                    int ri = hf * 2 + j;
                    float pr = acc[0][mt][nt][ri] + sb[coll + j];
                    float pz = acc[1][mt][nt][ri] + sb[64 + coll + j];
                    float rr = __fdividef(1.f, 1.f + __expf(-pr));
                    float zz = __fdividef(1.f, 1.f + __expf(-pz));
                    float pn = (acc[2][mt][nt][ri] + sb[128 + coll + j])
                             + rr * (acc[3][mt][nt][ri] + sb[192 + coll + j]);
                    float t  = __expf(-2.f * fabsf(pn));
                    float nn = copysignf(__fdividef(1.f - t, 1.f + t), pn);
                    float hv = j ? h2.y : h2.x;
                    o[j] = nn + zz * (hv - nn);
                }
                *reinterpret_cast<float2*>(out + base) = make_float2(o[0], o[1]);
            }
}

// --------------------------------------------------------------- launcher ---
extern "C" void kernel_launch(void* const* d_in, const int* in_sizes, int n_in,
                              void* d_out, int out_size) {
    const float* x   = (const float*)d_in[0];
    const float* hid = (const float*)d_in[1];
    const float* wx  = (const float*)d_in[2];
    const float* wh  = (const float*)d_in[3];
    const float* bx  = (const float*)d_in[4];
    const float* bh  = (const float*)d_in[5];
    float* out = (float*)d_out;

    cudaFuncSetAttribute(k_gru, cudaFuncAttributeMaxDynamicSharedMemorySize, SMEM_DYN);

    // merged pre-pass: 16384 convert blocks + 6144 weight-transpose blocks
    k_prep<<<22528, 256>>>(x, hid, wx, wh);
    // fused GEMM + GRU epilogue: 16 n-tiles x 64 m-tiles
    k_gru<<<dim3(16, 64), NTHREADS, SMEM_DYN>>>(hid, bx, bh, out);
}

// round 6
// speedup vs baseline: 1.6133x; 1.0270x over previous
#include <cuda_runtime.h>
#include <cuda_fp16.h>
#include <stdint.h>

// ============================================================================
// GRU cell via legacy mma.sync (tcgen05 unavailable at plain-sm_103 PTX target).
// R6: PERSISTENT grid (148 CTAs, ~7 tiles each). The 3-stage cp.async ring runs
// continuously across tile boundaries, so producers prefetch tile t+1 while
// consumers run tile t's epilogue — removes per-wave prologue/epilogue bubbles
// that held tensor pipe at 65%.
//   r = sigmoid(x@wx_r + hid@wh_r + b...), z = sigmoid(...),
//   n = tanh((x@wx_n + bx_n) + r*(hid@wh_n + bh_n)), out = (1-z)n + z*hid
// B=8192, I=H=1024. fp16 operands, fp32 accum, 4 register accumulator slots.
// CTA tile 128x64: 8 consumer warps (32x32) + 2 producer warps.
// ============================================================================

#define TM 128
#define TN 64
#define KC 64
#define STAGES 3
#define CHT 32                 // chunks per tile: 0..15 x-phase, 16..31 hid
#define NTILES 1024            // 64 m-tiles x 16 n-tiles
#define GRID 148
#define PITCH 144              // 128B row + 16B pad (conflict-free ldsm)
#define A_BYTES (128 * PITCH)              // 18432
#define WG_BYTES (64 * PITCH)              // 9216
#define STG (A_BYTES + 3 * WG_BYTES)       // 46080
#define SMEM_DYN (2048 + STAGES * STG)     // 140288

#define NTHREADS 320           // 8 consumer warps + 2 producer warps

// fp16 staging (device globals = allocation-free scratch)
__device__ __half g_xh[8192u * 1024u];
__device__ __half g_hh[8192u * 1024u];
__device__ __half g_wxh[3u * 1024u * 1024u];   // [g][h][i] (k contiguous)
__device__ __half g_whh[3u * 1024u * 1024u];

// ---------------------------------------------------------------- helpers ---
__device__ __forceinline__ uint32_t smem_u32(const void* p) {
    uint32_t a;
    asm("{ .reg .u64 t; cvta.to.shared.u64 t, %1; cvt.u32.u64 %0, t; }"
        : "=r"(a) : "l"(p));
    return a;
}

__device__ __forceinline__ void cp16(uint32_t dst, const void* src) {
    asm volatile("cp.async.cg.shared.global [%0], [%1], 16;\n"
                 :: "r"(dst), "l"(src));
}

__device__ __forceinline__ void ldsm4(uint32_t* r, uint32_t addr) {
    asm volatile("ldmatrix.sync.aligned.m8n8.x4.shared.b16 {%0,%1,%2,%3}, [%4];"
                 : "=r"(r[0]), "=r"(r[1]), "=r"(r[2]), "=r"(r[3]) : "r"(addr));
}

__device__ __forceinline__ void mma16816(float* c, const uint32_t* a, const uint32_t* b) {
    asm volatile(
        "mma.sync.aligned.m16n8k16.row.col.f32.f16.f16.f32 "
        "{%0,%1,%2,%3}, {%4,%5,%6,%7}, {%8,%9}, {%0,%1,%2,%3};"
        : "+f"(c[0]), "+f"(c[1]), "+f"(c[2]), "+f"(c[3])
        : "r"(a[0]), "r"(a[1]), "r"(a[2]), "r"(a[3]), "r"(b[0]), "r"(b[1]));
}

__device__ __forceinline__ void mbar_wait(uint32_t mbar, uint32_t parity) {
    asm volatile(
        "{\n\t.reg .pred P1;\n\t"
        "WL_%=:\n\t"
        "mbarrier.try_wait.parity.acquire.cta.shared::cta.b64 P1, [%0], %1, 0x989680;\n\t"
        "@P1 bra.uni WD_%=;\n\t"
        "bra.uni WL_%=;\n\t"
        "WD_%=:\n\t}"
        :: "r"(mbar), "r"(parity) : "memory");
}

__device__ __forceinline__ void mbar_arrive(uint32_t mbar) {
    asm volatile("mbarrier.arrive.shared.b64 _, [%0];" :: "r"(mbar) : "memory");
}

// ----------------------------------------------------- merged pre-pass ------
__global__ void k_prep(const float* __restrict__ x, const float* __restrict__ hid,
                       const float* __restrict__ wx, const float* __restrict__ wh) {
    const int b = blockIdx.x;
    if (b < 16384) {
        const float* src = (b < 8192) ? x : hid;
        __half* dst = (b < 8192) ? g_xh : g_hh;
        size_t i = ((size_t)(b & 8191) * 256 + threadIdx.x) * 4;
        float4 v = *reinterpret_cast<const float4*>(src + i);
        *reinterpret_cast<__half2*>(dst + i)     = __floats2half2_rn(v.x, v.y);
        *reinterpret_cast<__half2*>(dst + i + 2) = __floats2half2_rn(v.z, v.w);
        return;
    }
    __shared__ float tile[32][33];
    const int bb = b - 16384;
    const int m = bb >> 10;
    const int rem = bb & 1023;
    const int h0 = (rem & 31) * 32;
    const int i0 = (rem >> 5) * 32;
    const float* src = (m < 3) ? (wx + (size_t)m * 1048576)
                               : (wh + (size_t)(m - 3) * 1048576);
    __half* dst = ((m < 3) ? g_wxh : g_whh) + (size_t)(m % 3) * 1048576;
    const int tx = threadIdx.x & 31, ty = threadIdx.x >> 5;
#pragma unroll
    for (int j = 0; j < 32; j += 8)
        tile[ty + j][tx] = src[(size_t)(i0 + ty + j) * 1024 + h0 + tx];
    __syncthreads();
#pragma unroll
    for (int j = 0; j < 32; j += 8)
        dst[(size_t)(h0 + ty + j) * 1024 + i0 + tx] = __float2half_rn(tile[tx][ty + j]);
}

// ------------------------------------------------------------- GEMM kernel ---
// SMEM: [0,1024)    bias sb[4][64] fp32 (rewritten per tile, consumer-guarded)
//       [1024,1072) mbarriers: full[s]=1024+16s, empty[s]=1032+16s  (s=0..2)
//       [2048, ...) stages, each STG bytes: A[128][PITCH], then 3 W[64][PITCH]
// acc slots: 0=r, 1=z, 2=gx_n, 3=gh_n.

template<int NS>
__device__ __forceinline__ void compute_chunk(float (&acc)[4][2][4][4],
                                              uint32_t st, int lid, int wm, int wn) {
#pragma unroll
    for (int ks = 0; ks < 4; ks++) {
        uint32_t af[2][4];
#pragma unroll
        for (int mt = 0; mt < 2; mt++) {
            uint32_t arow = wm * 32 + mt * 16 + (lid & 15);
            ldsm4(af[mt], st + arow * PITCH + ks * 32 + (lid >> 4) * 16);
        }
#pragma unroll
        for (int g = 0; g < 3; g++) {
            const int slot = (g == 0) ? 0 : (g == 1) ? 1 : NS;
            uint32_t wg = st + A_BYTES + g * WG_BYTES;
            uint32_t bf[2][4];
#pragma unroll
            for (int p = 0; p < 2; p++) {
                uint32_t wrow = wn * 32 + p * 16 + (lid & 7) + ((lid & 16) >> 1);
                ldsm4(bf[p], wg + wrow * PITCH + ((lid >> 3) & 1) * 16 + ks * 32);
            }
#pragma unroll
            for (int mt = 0; mt < 2; mt++)
#pragma unroll
                for (int nt = 0; nt < 4; nt++)
                    mma16816(acc[slot][mt][nt], af[mt], &bf[nt >> 1][(nt & 1) * 2]);
        }
    }
}

__global__ void __launch_bounds__(NTHREADS, 1)
k_gru(const float* __restrict__ hid,
      const float* __restrict__ bx, const float* __restrict__ bh,
      float* __restrict__ out) {
    extern __shared__ char smem[];
    const uint32_t sbase = smem_u32(smem);
    const uint32_t mb0 = sbase + 1024;
    const uint32_t stg0 = sbase + 2048;

    const int tid = threadIdx.x;
    const int lid = tid & 31;
    const int wid = tid >> 5;
    const int bid = blockIdx.x;

    if (tid < STAGES) {
        asm volatile("mbarrier.init.shared.b64 [%0], 64;" :: "r"(mb0 + tid * 16)     : "memory");
        asm volatile("mbarrier.init.shared.b64 [%0], 8;"  :: "r"(mb0 + tid * 16 + 8) : "memory");
    }
    __syncthreads();

    if (wid >= 8) {
        // ---------------- producer warps: continuous across tiles --------------
        const int ptid = tid - 256;               // 0..63
        int c = 0;                                 // global chunk counter
        for (int t = bid; t < NTILES; t += GRID) {
            const int m0 = (t >> 4) * TM;
            const int n0 = (t & 15) * TN;
            for (int it = 0; it < CHT; ++it, ++c) {
                const int s = c % STAGES;
                const int rnd = c / STAGES;
                if (rnd > 0) mbar_wait(mb0 + s * 16 + 8, (rnd - 1) & 1);  // empty[s]
                uint32_t st = stg0 + (uint32_t)s * STG;
                const __half* asrc = (it < 16) ? g_xh  : g_hh;
                const __half* wsrc = (it < 16) ? g_wxh : g_whh;
                const int k0 = (it & 15) * KC;
#pragma unroll
                for (int q = 0; q < 16; q++) {     // A: 1024 cp16
                    int op = ptid + q * 64, row = op >> 3, cg = op & 7;
                    cp16(st + row * PITCH + cg * 16,
                         asrc + (size_t)(m0 + row) * 1024 + k0 + cg * 8);
                }
#pragma unroll
                for (int q = 0; q < 24; q++) {     // W: 1536 cp16
                    int op = ptid + q * 64, g = op >> 9, r = (op >> 3) & 63, cg = op & 7;
                    cp16(st + A_BYTES + g * WG_BYTES + r * PITCH + cg * 16,
                         wsrc + (size_t)g * 1048576 + (size_t)(n0 + r) * 1024 + k0 + cg * 8);
                }
                asm volatile("cp.async.mbarrier.arrive.noinc.shared::cta.b64 [%0];"
                             :: "r"(mb0 + s * 16) : "memory");
            }
        }
        return;
    }

    // ------------------- consumer warps (8 warps, 256 threads) ----------------
    const int wm = wid & 3;
    const int wn = wid >> 2;
    float* sb = reinterpret_cast<float*>(smem);
    const int g4 = lid >> 2, t4 = lid & 3;

    int c = 0;
    for (int t = bid; t < NTILES; t += GRID) {
        const int m0 = (t >> 4) * TM;
        const int n0 = (t & 15) * TN;

        // guard: previous tile's epilogue (sb readers) done before rewrite
        asm volatile("bar.sync 1, 256;" ::: "memory");
        if (tid < 64) {
            int h = n0 + tid;
            sb[tid]       = bx[h]        + bh[h];
            sb[64 + tid]  = bx[1024 + h] + bh[1024 + h];
            sb[128 + tid] = bx[2048 + h];
            sb[192 + tid] = bh[2048 + h];
        }
        asm volatile("bar.sync 1, 256;" ::: "memory");

        float acc[4][2][4][4];
#pragma unroll
        for (int s = 0; s < 4; s++)
#pragma unroll
            for (int mt = 0; mt < 2; mt++)
#pragma unroll
                for (int nt = 0; nt < 4; nt++)
#pragma unroll
                    for (int r = 0; r < 4; r++) acc[s][mt][nt][r] = 0.f;

#pragma unroll 1
        for (int it = 0; it < 16; ++it, ++c) {     // x-phase: n-gate -> slot 2
            const int s = c % STAGES;
            mbar_wait(mb0 + s * 16, (c / STAGES) & 1);
            compute_chunk<2>(acc, stg0 + (uint32_t)s * STG, lid, wm, wn);
            if (lid == 0) mbar_arrive(mb0 + s * 16 + 8);
        }
#pragma unroll 1
        for (int it = 16; it < CHT; ++it, ++c) {   // hid-phase: n-gate -> slot 3
            const int s = c % STAGES;
            mbar_wait(mb0 + s * 16, (c / STAGES) & 1);
            compute_chunk<3>(acc, stg0 + (uint32_t)s * STG, lid, wm, wn);
            if (lid == 0) mbar_arrive(mb0 + s * 16 + 8);
        }

        // ---- fused GRU epilogue (producers keep streaming next tile) ----
#pragma unroll
        for (int mt = 0; mt < 2; mt++)
#pragma unroll
            for (int nt = 0; nt < 4; nt++)
#pragma unroll
                for (int hf = 0; hf < 2; hf++) {
                    int row = m0 + wm * 32 + mt * 16 + g4 + hf * 8;
                    int coll = wn * 32 + nt * 8 + t4 * 2;
                    size_t base = (size_t)row * 1024 + n0 + coll;
                    float2 h2 = *reinterpret_cast<const float2*>(hid + base);
                    float o[2];
#pragma unroll
                    for (int j = 0; j < 2; j++) {
                        int ri = hf * 2 + j;
                        float pr = acc[0][mt][nt][ri] + sb[coll + j];
                        float pz = acc[1][mt][nt][ri] + sb[64 + coll + j];
                        float rr = __fdividef(1.f, 1.f + __expf(-pr));
                        float zz = __fdividef(1.f, 1.f + __expf(-pz));
                        float pn = (acc[2][mt][nt][ri] + sb[128 + coll + j])
                                 + rr * (acc[3][mt][nt][ri] + sb[192 + coll + j]);
                        float tt = __expf(-2.f * fabsf(pn));
                        float nn = copysignf(__fdividef(1.f - tt, 1.f + tt), pn);
                        float hv = j ? h2.y : h2.x;
                        o[j] = nn + zz * (hv - nn);
                    }
                    *reinterpret_cast<float2*>(out + base) = make_float2(o[0], o[1]);
                }
    }
}

// --------------------------------------------------------------- launcher ---
extern "C" void kernel_launch(void* const* d_in, const int* in_sizes, int n_in,
                              void* d_out, int out_size) {
    const float* x   = (const float*)d_in[0];
    const float* hid = (const float*)d_in[1];
    const float* wx  = (const float*)d_in[2];
    const float* wh  = (const float*)d_in[3];
    const float* bx  = (const float*)d_in[4];
    const float* bh  = (const float*)d_in[5];
    float* out = (float*)d_out;

    cudaFuncSetAttribute(k_gru, cudaFuncAttributeMaxDynamicSharedMemorySize, SMEM_DYN);

    k_prep<<<22528, 256>>>(x, hid, wx, wh);
    k_gru<<<GRID, NTHREADS, SMEM_DYN>>>(hid, bx, bh, out);
}

// round 7
// speedup vs baseline: 1.6618x; 1.0301x over previous
#include <cuda_runtime.h>
#include <cuda_fp16.h>
#include <stdint.h>

// ============================================================================
// GRU cell via legacy mma.sync (tcgen05 unavailable at plain-sm_103 PTX target).
// R7: (1) producers stage the epilogue's hid tile into double-buffered SMEM
// (kills 16 dependent gmem loads/thread in the epilogue); (2) grouped ldsm
// (all 8 per ks-step before the 24 MMAs) to shrink ldsm->MMA dependency
// shadows. Persistent grid (148 CTAs), 3-stage chunk ring, warp-specialized.
//   r = sigmoid(x@wx_r + hid@wh_r + b...), z = sigmoid(...),
//   n = tanh((x@wx_n + bx_n) + r*(hid@wh_n + bh_n)), out = (1-z)n + z*hid
// B=8192, I=H=1024. fp16 operands, fp32 accum, 4 register accumulator slots.
// ============================================================================

#define TM 128
#define TN 64
#define KC 64
#define STAGES 3
#define CHT 32                 // chunks per tile: 0..15 x-phase, 16..31 hid
#define NTILES 1024            // 64 m-tiles x 16 n-tiles
#define GRID 148
#define PITCH 144              // 128B row + 16B pad (conflict-free ldsm)
#define A_BYTES (128 * PITCH)              // 18432
#define WG_BYTES (64 * PITCH)              // 9216
#define STG (A_BYTES + 3 * WG_BYTES)       // 46080
#define HIDB (2048 + STAGES * STG)         // 140288: hid tiles start
#define HPITCH 272                          // 64 floats + 16B pad (16B-aligned)
#define HBYTES (128 * HPITCH)              // 34816 per parity
#define SMEM_DYN (HIDB + 2 * HBYTES)       // 209920

#define NTHREADS 320           // 8 consumer warps + 2 producer warps

// fp16 staging (device globals = allocation-free scratch)
__device__ __half g_xh[8192u * 1024u];
__device__ __half g_hh[8192u * 1024u];
__device__ __half g_wxh[3u * 1024u * 1024u];   // [g][h][i] (k contiguous)
__device__ __half g_whh[3u * 1024u * 1024u];

// ---------------------------------------------------------------- helpers ---
__device__ __forceinline__ uint32_t smem_u32(const void* p) {
    uint32_t a;
    asm("{ .reg .u64 t; cvta.to.shared.u64 t, %1; cvt.u32.u64 %0, t; }"
        : "=r"(a) : "l"(p));
    return a;
}

__device__ __forceinline__ void cp16(uint32_t dst, const void* src) {
    asm volatile("cp.async.cg.shared.global [%0], [%1], 16;\n"
                 :: "r"(dst), "l"(src));
}

__device__ __forceinline__ void ldsm4(uint32_t* r, uint32_t addr) {
    asm volatile("ldmatrix.sync.aligned.m8n8.x4.shared.b16 {%0,%1,%2,%3}, [%4];"
                 : "=r"(r[0]), "=r"(r[1]), "=r"(r[2]), "=r"(r[3]) : "r"(addr));
}

__device__ __forceinline__ void mma16816(float* c, const uint32_t* a, const uint32_t* b) {
    asm volatile(
        "mma.sync.aligned.m16n8k16.row.col.f32.f16.f16.f32 "
        "{%0,%1,%2,%3}, {%4,%5,%6,%7}, {%8,%9}, {%0,%1,%2,%3};"
        : "+f"(c[0]), "+f"(c[1]), "+f"(c[2]), "+f"(c[3])
        : "r"(a[0]), "r"(a[1]), "r"(a[2]), "r"(a[3]), "r"(b[0]), "r"(b[1]));
}

__device__ __forceinline__ void mbar_wait(uint32_t mbar, uint32_t parity) {
    asm volatile(
        "{\n\t.reg .pred P1;\n\t"
        "WL_%=:\n\t"
        "mbarrier.try_wait.parity.acquire.cta.shared::cta.b64 P1, [%0], %1, 0x989680;\n\t"
        "@P1 bra.uni WD_%=;\n\t"
        "bra.uni WL_%=;\n\t"
        "WD_%=:\n\t}"
        :: "r"(mbar), "r"(parity) : "memory");
}

__device__ __forceinline__ void mbar_arrive(uint32_t mbar) {
    asm volatile("mbarrier.arrive.shared.b64 _, [%0];" :: "r"(mbar) : "memory");
}

// ----------------------------------------------------- merged pre-pass ------
__global__ void k_prep(const float* __restrict__ x, const float* __restrict__ hid,
                       const float* __restrict__ wx, const float* __restrict__ wh) {
    const int b = blockIdx.x;
    if (b < 16384) {
        const float* src = (b < 8192) ? x : hid;
        __half* dst = (b < 8192) ? g_xh : g_hh;
        size_t i = ((size_t)(b & 8191) * 256 + threadIdx.x) * 4;
        float4 v = *reinterpret_cast<const float4*>(src + i);
        *reinterpret_cast<__half2*>(dst + i)     = __floats2half2_rn(v.x, v.y);
        *reinterpret_cast<__half2*>(dst + i + 2) = __floats2half2_rn(v.z, v.w);
        return;
    }
    __shared__ float tile[32][33];
    const int bb = b - 16384;
    const int m = bb >> 10;
    const int rem = bb & 1023;
    const int h0 = (rem & 31) * 32;
    const int i0 = (rem >> 5) * 32;
    const float* src = (m < 3) ? (wx + (size_t)m * 1048576)
                               : (wh + (size_t)(m - 3) * 1048576);
    __half* dst = ((m < 3) ? g_wxh : g_whh) + (size_t)(m % 3) * 1048576;
    const int tx = threadIdx.x & 31, ty = threadIdx.x >> 5;
#pragma unroll
    for (int j = 0; j < 32; j += 8)
        tile[ty + j][tx] = src[(size_t)(i0 + ty + j) * 1024 + h0 + tx];
    __syncthreads();
#pragma unroll
    for (int j = 0; j < 32; j += 8)
        dst[(size_t)(h0 + ty + j) * 1024 + i0 + tx] = __float2half_rn(tile[tx][ty + j]);
}

// ------------------------------------------------------------- GEMM kernel ---
// SMEM: [0,1024)      bias sb[4][64] fp32 (per tile, consumer-guarded)
//       [1024,1072)   chunk mbarriers: full[s]=1024+16s, empty[s]=1032+16s
//       [1104,1136)   hid mbarriers: hfull[p]=1104+16p, hempty[p]=1112+16p
//       [2048,140288) chunk stages: A[128][PITCH] + 3 W[64][PITCH] each
//       [140288, ...) hid tiles: parity p at HIDB + p*HBYTES, pitch HPITCH
// acc slots: 0=r, 1=z, 2=gx_n, 3=gh_n.

template<int NS>
__device__ __forceinline__ void compute_chunk(float (&acc)[4][2][4][4],
                                              uint32_t st, int lid, int wm, int wn) {
#pragma unroll
    for (int ks = 0; ks < 4; ks++) {
        uint32_t af[2][4];
        uint32_t bf[3][2][4];
#pragma unroll
        for (int mt = 0; mt < 2; mt++) {
            uint32_t arow = wm * 32 + mt * 16 + (lid & 15);
            ldsm4(af[mt], st + arow * PITCH + ks * 32 + (lid >> 4) * 16);
        }
#pragma unroll
        for (int g = 0; g < 3; g++)
#pragma unroll
            for (int p = 0; p < 2; p++) {
                uint32_t wrow = wn * 32 + p * 16 + (lid & 7) + ((lid & 16) >> 1);
                ldsm4(bf[g][p], st + A_BYTES + g * WG_BYTES + wrow * PITCH
                                 + ((lid >> 3) & 1) * 16 + ks * 32);
            }
#pragma unroll
        for (int g = 0; g < 3; g++) {
            const int slot = (g == 0) ? 0 : (g == 1) ? 1 : NS;
#pragma unroll
            for (int mt = 0; mt < 2; mt++)
#pragma unroll
                for (int nt = 0; nt < 4; nt++)
                    mma16816(acc[slot][mt][nt], af[mt], &bf[g][nt >> 1][(nt & 1) * 2]);
        }
    }
}

__global__ void __launch_bounds__(NTHREADS, 1)
k_gru(const float* __restrict__ hid,
      const float* __restrict__ bx, const float* __restrict__ bh,
      float* __restrict__ out) {
    extern __shared__ char smem[];
    const uint32_t sbase = smem_u32(smem);
    const uint32_t mb0 = sbase + 1024;
    const uint32_t hmb = sbase + 1104;
    const uint32_t stg0 = sbase + 2048;

    const int tid = threadIdx.x;
    const int lid = tid & 31;
    const int wid = tid >> 5;
    const int bid = blockIdx.x;

    if (tid < STAGES) {
        asm volatile("mbarrier.init.shared.b64 [%0], 64;" :: "r"(mb0 + tid * 16)     : "memory");
        asm volatile("mbarrier.init.shared.b64 [%0], 8;"  :: "r"(mb0 + tid * 16 + 8) : "memory");
    }
    if (tid >= 32 && tid < 34) {
        int p = tid - 32;
        asm volatile("mbarrier.init.shared.b64 [%0], 64;" :: "r"(hmb + p * 16)     : "memory");
        asm volatile("mbarrier.init.shared.b64 [%0], 8;"  :: "r"(hmb + p * 16 + 8) : "memory");
    }
    __syncthreads();

    if (wid >= 8) {
        // ---------------- producer warps: continuous across tiles --------------
        const int ptid = tid - 256;               // 0..63
        int c = 0;                                 // global chunk counter
        int tt = 0;                                // tile sequence counter
        for (int t = bid; t < NTILES; t += GRID, ++tt) {
            const int m0 = (t >> 4) * TM;
            const int n0 = (t & 15) * TN;
            const int p = tt & 1;
            const int r = tt >> 1;
            // stage hid tile for the epilogue (double-buffered)
            if (r > 0) mbar_wait(hmb + p * 16 + 8, (r - 1) & 1);   // hempty[p]
            {
                uint32_t hb = stg0 - 2048 + sbase + 0;  // placate compiler (unused)
                (void)hb;
                uint32_t hdst = sbase + HIDB + (uint32_t)p * HBYTES;
#pragma unroll
                for (int q = 0; q < 32; q++) {      // 2048 cp16: 128 rows x 16
                    int op = ptid + q * 64, row = op >> 4, cg = op & 15;
                    cp16(hdst + row * HPITCH + cg * 16,
                         hid + (size_t)(m0 + row) * 1024 + n0 + cg * 4);
                }
                asm volatile("cp.async.mbarrier.arrive.noinc.shared::cta.b64 [%0];"
                             :: "r"(hmb + p * 16) : "memory");      // hfull[p]
            }
            for (int it = 0; it < CHT; ++it, ++c) {
                const int s = c % STAGES;
                const int rnd = c / STAGES;
                if (rnd > 0) mbar_wait(mb0 + s * 16 + 8, (rnd - 1) & 1);  // empty[s]
                uint32_t st = stg0 + (uint32_t)s * STG;
                const __half* asrc = (it < 16) ? g_xh  : g_hh;
                const __half* wsrc = (it < 16) ? g_wxh : g_whh;
                const int k0 = (it & 15) * KC;
#pragma unroll
                for (int q = 0; q < 16; q++) {     // A: 1024 cp16
                    int op = ptid + q * 64, row = op >> 3, cg = op & 7;
                    cp16(st + row * PITCH + cg * 16,
                         asrc + (size_t)(m0 + row) * 1024 + k0 + cg * 8);
                }
#pragma unroll
                for (int q = 0; q < 24; q++) {     // W: 1536 cp16
                    int op = ptid + q * 64, g = op >> 9, rr2 = (op >> 3) & 63, cg = op & 7;
                    cp16(st + A_BYTES + g * WG_BYTES + rr2 * PITCH + cg * 16,
                         wsrc + (size_t)g * 1048576 + (size_t)(n0 + rr2) * 1024 + k0 + cg * 8);
                }
                asm volatile("cp.async.mbarrier.arrive.noinc.shared::cta.b64 [%0];"
                             :: "r"(mb0 + s * 16) : "memory");
            }
        }
        return;
    }

    // ------------------- consumer warps (8 warps, 256 threads) ----------------
    const int wm = wid & 3;
    const int wn = wid >> 2;
    float* sb = reinterpret_cast<float*>(smem);
    const int g4 = lid >> 2, t4 = lid & 3;

    int c = 0;
    int tt = 0;
    for (int t = bid; t < NTILES; t += GRID, ++tt) {
        const int m0 = (t >> 4) * TM;
        const int n0 = (t & 15) * TN;
        const int p = tt & 1;
        const int r = tt >> 1;

        // guard: previous tile's epilogue (sb readers) done before rewrite
        asm volatile("bar.sync 1, 256;" ::: "memory");
        if (tid < 64) {
            int h = n0 + tid;
            sb[tid]       = bx[h]        + bh[h];
            sb[64 + tid]  = bx[1024 + h] + bh[1024 + h];
            sb[128 + tid] = bx[2048 + h];
            sb[192 + tid] = bh[2048 + h];
        }
        asm volatile("bar.sync 1, 256;" ::: "memory");

        float acc[4][2][4][4];
#pragma unroll
        for (int s = 0; s < 4; s++)
#pragma unroll
            for (int mt = 0; mt < 2; mt++)
#pragma unroll
                for (int nt = 0; nt < 4; nt++)
#pragma unroll
                    for (int q = 0; q < 4; q++) acc[s][mt][nt][q] = 0.f;

#pragma unroll 1
        for (int it = 0; it < 16; ++it, ++c) {     // x-phase: n-gate -> slot 2
            const int s = c % STAGES;
            mbar_wait(mb0 + s * 16, (c / STAGES) & 1);
            compute_chunk<2>(acc, stg0 + (uint32_t)s * STG, lid, wm, wn);
            if (lid == 0) mbar_arrive(mb0 + s * 16 + 8);
        }
#pragma unroll 1
        for (int it = 16; it < CHT; ++it, ++c) {   // hid-phase: n-gate -> slot 3
            const int s = c % STAGES;
            mbar_wait(mb0 + s * 16, (c / STAGES) & 1);
            compute_chunk<3>(acc, stg0 + (uint32_t)s * STG, lid, wm, wn);
            if (lid == 0) mbar_arrive(mb0 + s * 16 + 8);
        }

        // ---- fused GRU epilogue (hid from SMEM; producers stream next tile) ----
        mbar_wait(hmb + p * 16, r & 1);            // hfull[p]
        const char* hbuf = smem + HIDB + (size_t)p * HBYTES;
#pragma unroll
        for (int mt = 0; mt < 2; mt++)
#pragma unroll
            for (int nt = 0; nt < 4; nt++)
#pragma unroll
                for (int hf = 0; hf < 2; hf++) {
                    int rloc = wm * 32 + mt * 16 + g4 + hf * 8;
                    int coll = wn * 32 + nt * 8 + t4 * 2;
                    float2 h2 = *reinterpret_cast<const float2*>(
                        hbuf + rloc * HPITCH + coll * 4);
                    size_t base = (size_t)(m0 + rloc) * 1024 + n0 + coll;
                    float o[2];
#pragma unroll
                    for (int j = 0; j < 2; j++) {
                        int ri = hf * 2 + j;
                        float pr = acc[0][mt][nt][ri] + sb[coll + j];
                        float pz = acc[1][mt][nt][ri] + sb[64 + coll + j];
                        float rr = __fdividef(1.f, 1.f + __expf(-pr));
                        float zz = __fdividef(1.f, 1.f + __expf(-pz));
                        float pn = (acc[2][mt][nt][ri] + sb[128 + coll + j])
                                 + rr * (acc[3][mt][nt][ri] + sb[192 + coll + j]);
                        float ttv = __expf(-2.f * fabsf(pn));
                        float nn = copysignf(__fdividef(1.f - ttv, 1.f + ttv), pn);
                        float hv = j ? h2.y : h2.x;
                        o[j] = nn + zz * (hv - nn);
                    }
                    *reinterpret_cast<float2*>(out + base) = make_float2(o[0], o[1]);
                }
        if (lid == 0) mbar_arrive(hmb + p * 16 + 8);   // hempty[p]
    }
}

// --------------------------------------------------------------- launcher ---
extern "C" void kernel_launch(void* const* d_in, const int* in_sizes, int n_in,
                              void* d_out, int out_size) {
    const float* x   = (const float*)d_in[0];
    const float* hid = (const float*)d_in[1];
    const float* wx  = (const float*)d_in[2];
    const float* wh  = (const float*)d_in[3];
    const float* bx  = (const float*)d_in[4];
    const float* bh  = (const float*)d_in[5];
    float* out = (float*)d_out;

    cudaFuncSetAttribute(k_gru, cudaFuncAttributeMaxDynamicSharedMemorySize, SMEM_DYN);

    k_prep<<<22528, 256>>>(x, hid, wx, wh);
    k_gru<<<GRID, NTHREADS, SMEM_DYN>>>(hid, bx, bh, out);
}